// round 7
// baseline (speedup 1.0000x reference)
#include <cuda_runtime.h>
#include <cstdint>

#define NUM_CLASSES 100000
#define BATCH 512
#define EMBED 512

#define S_SCALE 64.0f
#define COS_M 0.8775825618903728f
#define SIN_M 0.479425538604203f
#define TH_V (-0.8775825618903728f)
#define MM_V 0.23971276930210156f

// scratch (no allocations allowed)
// Interleaved int8 quantization: per row, group g (elements 4g..4g+3):
//   bytes [8g..8g+3] = q1 (coarse int8 x4), [8g+4..8g+7] = q2 (fine int8 x4)
__device__ int2  g_wq[(size_t)NUM_CLASSES * (EMBED / 4)];  // 102.4 MB
__device__ int2  g_xq[(size_t)BATCH * (EMBED / 4)];
__device__ float g_swf[NUM_CLASSES];   // per-class scale (includes 1/||w||)
__device__ float g_sxf[BATCH];         // per-row scale of x
__device__ float g_rownll[BATCH];
__device__ int   g_label[BATCH];

// ---------------------------------------------------------------------------
// helpers
// ---------------------------------------------------------------------------
__device__ __forceinline__ uint32_t smem_u32(const void* p) {
    return (uint32_t)__cvta_generic_to_shared(p);
}
__device__ __forceinline__ void cp_async16(uint32_t sdst, const void* gsrc, bool pred) {
    int sz = pred ? 16 : 0;   // sz=0 -> zero-fill (cp.async src-size semantics)
    asm volatile("cp.async.cg.shared.global [%0], [%1], 16, %2;\n"
                 :: "r"(sdst), "l"(gsrc), "r"(sz));
}
__device__ __forceinline__ void lds64(uint32_t& lo, uint32_t& hi, uint32_t addr) {
    asm volatile("ld.shared.v2.b32 {%0, %1}, [%2];" : "=r"(lo), "=r"(hi) : "r"(addr));
}
__device__ __forceinline__ void imma(int* d, const uint32_t* a, const uint32_t* b) {
    asm volatile(
        "mma.sync.aligned.m16n8k32.row.col.s32.s8.s8.s32 "
        "{%0,%1,%2,%3}, {%4,%5,%6,%7}, {%8,%9}, {%0,%1,%2,%3};\n"
        : "+r"(d[0]), "+r"(d[1]), "+r"(d[2]), "+r"(d[3])
        : "r"(a[0]), "r"(a[1]), "r"(a[2]), "r"(a[3]), "r"(b[0]), "r"(b[1]));
}
__device__ __forceinline__ uint32_t pack4(int a, int b, int c, int d) {
    return (a & 0xFF) | ((b & 0xFF) << 8) | ((c & 0xFF) << 16) | ((d & 0xFF) << 24);
}

// ---------------------------------------------------------------------------
// K0: label dtype autodetect (int64 vs int32) + materialize int32 labels.
// ---------------------------------------------------------------------------
__global__ void label_kernel(const int* __restrict__ raw) {
    __shared__ int s_or[16];
    int tid = threadIdx.x;
    int v = (tid & 1) ? raw[tid] : 0;
#pragma unroll
    for (int o = 16; o; o >>= 1) v |= __shfl_xor_sync(0xffffffffu, v, o);
    if ((tid & 31) == 0) s_or[tid >> 5] = v;
    __syncthreads();
    if (tid < 16) {
        int w = s_or[tid];
#pragma unroll
        for (int o = 8; o; o >>= 1) w |= __shfl_xor_sync(0xffffu, w, o);
        if (tid == 0) s_or[0] = w;
    }
    __syncthreads();
    bool is64 = (s_or[0] == 0);
    g_label[tid] = is64 ? raw[2 * tid] : raw[tid];
}

// ---------------------------------------------------------------------------
// K1a: W prep — norm + amax in one pass, then 2-term int8 quantize.
// One warp per class row. u = w * 127/amax (normalization cancels in u);
// scale swf = amax / (127 * ||w||).
// ---------------------------------------------------------------------------
__global__ void wquant_kernel(const float* __restrict__ w) {
    int gw   = (blockIdx.x * blockDim.x + threadIdx.x) >> 5;
    int lane = threadIdx.x & 31;
    if (gw >= NUM_CLASSES) return;
    const float4* row = (const float4*)(w + (size_t)gw * EMBED);
    float4 v[4];
    float ss = 0.f, am = 0.f;
#pragma unroll
    for (int i = 0; i < 4; i++) {
        v[i] = row[lane + i * 32];
        ss += v[i].x * v[i].x + v[i].y * v[i].y + v[i].z * v[i].z + v[i].w * v[i].w;
        am = fmaxf(am, fmaxf(fmaxf(fabsf(v[i].x), fabsf(v[i].y)),
                             fmaxf(fabsf(v[i].z), fabsf(v[i].w))));
    }
#pragma unroll
    for (int o = 16; o; o >>= 1) {
        ss += __shfl_xor_sync(0xffffffffu, ss, o);
        am = fmaxf(am, __shfl_xor_sync(0xffffffffu, am, o));
    }
    float norm = fmaxf(__fsqrt_rn(ss), 1e-12f);
    am = fmaxf(am, 1e-30f);
    float invq = 127.0f / am;
    int2* dst = g_wq + (size_t)gw * (EMBED / 4);
#pragma unroll
    for (int i = 0; i < 4; i++) {
        int g = lane + i * 32;
        float u0 = v[i].x * invq, u1 = v[i].y * invq, u2 = v[i].z * invq, u3 = v[i].w * invq;
        int q0 = (int)rintf(u0), q1 = (int)rintf(u1), q2 = (int)rintf(u2), q3 = (int)rintf(u3);
        int r0 = (int)rintf((u0 - q0) * 128.f), r1 = (int)rintf((u1 - q1) * 128.f);
        int r2 = (int)rintf((u2 - q2) * 128.f), r3 = (int)rintf((u3 - q3) * 128.f);
        int2 o;
        o.x = (int)pack4(q0, q1, q2, q3);
        o.y = (int)pack4(r0, r1, r2, r3);
        dst[g] = o;
    }
    if (lane == 0) g_swf[gw] = am / (127.0f * norm);
}

// K1b: X prep — per-row amax + 2-term int8 quantize. One warp per batch row.
__global__ void xquant_kernel(const float* __restrict__ x) {
    int gw   = (blockIdx.x * blockDim.x + threadIdx.x) >> 5;
    int lane = threadIdx.x & 31;
    if (gw >= BATCH) return;
    const float4* row = (const float4*)(x + (size_t)gw * EMBED);
    float4 v[4];
    float am = 0.f;
#pragma unroll
    for (int i = 0; i < 4; i++) {
        v[i] = row[lane + i * 32];
        am = fmaxf(am, fmaxf(fmaxf(fabsf(v[i].x), fabsf(v[i].y)),
                             fmaxf(fabsf(v[i].z), fabsf(v[i].w))));
    }
#pragma unroll
    for (int o = 16; o; o >>= 1) am = fmaxf(am, __shfl_xor_sync(0xffffffffu, am, o));
    am = fmaxf(am, 1e-30f);
    float invq = 127.0f / am;
    int2* dst = g_xq + (size_t)gw * (EMBED / 4);
#pragma unroll
    for (int i = 0; i < 4; i++) {
        int g = lane + i * 32;
        float u0 = v[i].x * invq, u1 = v[i].y * invq, u2 = v[i].z * invq, u3 = v[i].w * invq;
        int q0 = (int)rintf(u0), q1 = (int)rintf(u1), q2 = (int)rintf(u2), q3 = (int)rintf(u3);
        int r0 = (int)rintf((u0 - q0) * 128.f), r1 = (int)rintf((u1 - q1) * 128.f);
        int r2 = (int)rintf((u2 - q2) * 128.f), r3 = (int)rintf((u3 - q3) * 128.f);
        int2 o;
        o.x = (int)pack4(q0, q1, q2, q3);
        o.y = (int)pack4(r0, r1, r2, r3);
        dst[g] = o;
    }
    if (lane == 0) g_sxf[gw] = am / 127.0f;
}

// ---------------------------------------------------------------------------
// K2: 3-term int8 GEMM (mma.sync m16n8k32 s8, s32 accum) + ArcFace epilogue.
//   cos[m,n] = sx[m]*sw[n]*(main + cross/128)
// BM=128 batch, BN=64 class, BK=32. 256 threads, 8 warps 2x4, warp tile 64x16.
// smem row = 64B payload (8 groups of [q1x4|q2x4]), stride 112B
// (16B-aligned, bank-conflict-free). cp.async double-buffered.
// ---------------------------------------------------------------------------
#define BM 128
#define BN 64
#define BK 32
#define RSTRIDE 112
#define NKT (EMBED / BK)   // 16

__global__ void __launch_bounds__(256, 2)
arcface_gemm_i8(float* __restrict__ out) {
    __shared__ __align__(16) uint8_t s_xq[2][BM * RSTRIDE];   // 2 x 14336
    __shared__ __align__(16) uint8_t s_wq[2][BN * RSTRIDE];   // 2 x 7168

    const int m0 = blockIdx.x * BM;        // 4 batch tiles (fast dim)
    const int n0 = blockIdx.y * BN;        // 1563 class tiles
    const int tid  = threadIdx.x;
    const int warp = tid >> 5, lane = tid & 31;
    const int wm = warp >> 2, wn = warp & 3;    // 2 x 4 warp grid
    const int grp = lane >> 2, tig = lane & 3;

    int mainA[4][2][4], crossA[4][2][4];
#pragma unroll
    for (int i = 0; i < 4; i++)
#pragma unroll
        for (int j = 0; j < 2; j++)
#pragma unroll
            for (int k = 0; k < 4; k++) { mainA[i][j][k] = 0; crossA[i][j][k] = 0; }

    // loader: X 512 chunks + W 256 chunks of 16B over 256 threads -> 3 each
    auto load_tiles = [&](int t, int buf) {
#pragma unroll
        for (int j = 0; j < 2; j++) {       // X
            int id  = tid + j * 256;
            int row = id >> 2, c16 = id & 3;
            cp_async16(smem_u32(&s_xq[buf][row * RSTRIDE + c16 * 16]),
                       (const char*)g_xq + (size_t)(m0 + row) * 1024 + t * 64 + c16 * 16,
                       true);
        }
        {                                    // W
            int row = tid >> 2, c16 = tid & 3;
            cp_async16(smem_u32(&s_wq[buf][row * RSTRIDE + c16 * 16]),
                       (const char*)g_wq + (size_t)(n0 + row) * 1024 + t * 64 + c16 * 16,
                       (n0 + row) < NUM_CLASSES);
        }
        asm volatile("cp.async.commit_group;" ::: "memory");
    };

    load_tiles(0, 0);

    for (int t = 0; t < NKT; t++) {
        if (t + 1 < NKT) {
            load_tiles(t + 1, (t + 1) & 1);
            asm volatile("cp.async.wait_group 1;" ::: "memory");
        } else {
            asm volatile("cp.async.wait_group 0;" ::: "memory");
        }
        __syncthreads();

        const uint32_t xb = smem_u32(&s_xq[t & 1][0]);
        const uint32_t wb = smem_u32(&s_wq[t & 1][0]);

        // B fragments: w1/w2 interleaved -> LDS.64 pairs
        uint32_t w1f[2][2], w2f[2][2];
#pragma unroll
        for (int nt = 0; nt < 2; nt++) {
            uint32_t base = wb + (wn * 16 + nt * 8 + grp) * RSTRIDE + 8 * tig;
            lds64(w1f[nt][0], w2f[nt][0], base);
            lds64(w1f[nt][1], w2f[nt][1], base + 32);
        }
#pragma unroll
        for (int mt = 0; mt < 4; mt++) {
            uint32_t x1[4], x2[4];
            uint32_t base = xb + (wm * 64 + mt * 16 + grp) * RSTRIDE + 8 * tig;
            lds64(x1[0], x2[0], base);
            lds64(x1[2], x2[2], base + 32);
            lds64(x1[1], x2[1], base + 8 * RSTRIDE);
            lds64(x1[3], x2[3], base + 8 * RSTRIDE + 32);
#pragma unroll
            for (int nt = 0; nt < 2; nt++) {
                imma(mainA[mt][nt],  x1, w1f[nt]);
                imma(crossA[mt][nt], x1, w2f[nt]);
                imma(crossA[mt][nt], x2, w1f[nt]);
            }
        }
        __syncthreads();
    }

    // Epilogue: dequant, ArcFace margin at label column, * S.
#pragma unroll
    for (int mt = 0; mt < 4; mt++) {
        int m_lo = m0 + wm * 64 + mt * 16 + grp;
        int m_hi = m_lo + 8;
        float sx_lo = g_sxf[m_lo], sx_hi = g_sxf[m_hi];
        int lbl_lo = g_label[m_lo], lbl_hi = g_label[m_hi];
#pragma unroll
        for (int nt = 0; nt < 2; nt++) {
            int n = n0 + wn * 16 + nt * 8 + 2 * tig;
            bool v0 = n < NUM_CLASSES;
            bool v1 = (n + 1) < NUM_CLASSES;
            float sw0 = v0 ? g_swf[n] : 0.f;
            float sw1 = v1 ? g_swf[n + 1] : 0.f;
            const int* ma = mainA[mt][nt];
            const int* cr = crossA[mt][nt];
#pragma unroll
            for (int e = 0; e < 4; e++) {
                bool hiRow = (e >= 2);
                bool odd   = (e & 1);
                if (odd ? !v1 : !v0) continue;
                float scale = (hiRow ? sx_hi : sx_lo) * (odd ? sw1 : sw0);
                float c = fmaf((float)cr[e], 0.0078125f, (float)ma[e]) * scale;
                int nn  = n + (odd ? 1 : 0);
                int lbl = hiRow ? lbl_hi : lbl_lo;
                if (nn == lbl) {
                    float s2 = fminf(fmaxf(1.0f - c * c, 0.0f), 1.0f);
                    float phi = c * COS_M - sqrtf(s2) * SIN_M;
                    c = (c > TH_V) ? phi : (c - MM_V);
                }
                int m = hiRow ? m_hi : m_lo;
                out[(size_t)m * NUM_CLASSES + nn] = c * S_SCALE;
            }
        }
    }
}

// ---------------------------------------------------------------------------
// K3: per-row online logsumexp over 100000 logits -> per-row NLL.
// ---------------------------------------------------------------------------
__global__ void lse_kernel(const float* __restrict__ logits) {
    const int row = blockIdx.x;
    const int tid = threadIdx.x;
    const float4* p = (const float4*)(logits + (size_t)row * NUM_CLASSES);
    const int n4 = NUM_CLASSES / 4;

    float m = -INFINITY, s = 0.f;
    for (int i = tid; i < n4; i += 512) {
        float4 v = p[i];
        float mx = fmaxf(fmaxf(v.x, v.y), fmaxf(v.z, v.w));
        if (mx > m) { s *= __expf(m - mx); m = mx; }
        s += __expf(v.x - m) + __expf(v.y - m) + __expf(v.z - m) + __expf(v.w - m);
    }

    __shared__ float sm[512];
    __shared__ float ss[512];
    sm[tid] = m; ss[tid] = s;
    __syncthreads();
    for (int o = 256; o; o >>= 1) {
        if (tid < o) {
            float m1 = sm[tid], s1 = ss[tid];
            float m2 = sm[tid + o], s2 = ss[tid + o];
            float mm = fmaxf(m1, m2);
            sm[tid] = mm;
            ss[tid] = s1 * __expf(m1 - mm) + s2 * __expf(m2 - mm);
        }
        __syncthreads();
    }
    if (tid == 0) {
        float logZ = sm[0] + __logf(ss[0]);
        int lbl = g_label[row];
        g_rownll[row] = logZ - logits[(size_t)row * NUM_CLASSES + lbl];
    }
}

// ---------------------------------------------------------------------------
// K4: loss = mean(rownll).
// ---------------------------------------------------------------------------
__global__ void loss_kernel(float* __restrict__ out, int out_size) {
    __shared__ float sm[BATCH];
    sm[threadIdx.x] = g_rownll[threadIdx.x];
    __syncthreads();
    for (int o = 256; o; o >>= 1) {
        if (threadIdx.x < o) sm[threadIdx.x] += sm[threadIdx.x + o];
        __syncthreads();
    }
    if (threadIdx.x == 0) {
        long long total = (long long)BATCH * NUM_CLASSES;
        if ((long long)out_size > total)
            out[total] = sm[0] * (1.0f / BATCH);
    }
}

// ---------------------------------------------------------------------------
extern "C" void kernel_launch(void* const* d_in, const int* in_sizes, int n_in,
                              void* d_out, int out_size) {
    const float* X        = (const float*)d_in[0];
    const int*   labelRaw = (const int*)d_in[1];
    const float* W        = (const float*)d_in[2];
    float* out = (float*)d_out;

    label_kernel<<<1, BATCH>>>(labelRaw);
    xquant_kernel<<<BATCH / 8, 256>>>(X);
    wquant_kernel<<<NUM_CLASSES / 8, 256>>>(W);

    dim3 grid(BATCH / BM, (NUM_CLASSES + BN - 1) / BN);   // (4, 1563)
    arcface_gemm_i8<<<grid, 256>>>(out);

    lse_kernel<<<BATCH, 512>>>(out);
    loss_kernel<<<1, BATCH>>>(out, out_size);
}

// round 8
// speedup vs baseline: 3.7276x; 3.7276x over previous
#include <cuda_runtime.h>
#include <cuda_fp16.h>
#include <cstdint>

#define NUM_CLASSES 100000
#define BATCH 512
#define EMBED 512

#define S_SCALE 64.0f
#define COS_M 0.8775825618903728f
#define SIN_M 0.479425538604203f
#define TH_V (-0.8775825618903728f)
#define MM_V 0.23971276930210156f

// scratch (no allocations allowed)
__device__ __half g_wh[(size_t)NUM_CLASSES * EMBED];  // fp16(w / ||w||)
__device__ __half g_xh[BATCH * EMBED];                // fp16(x)
__device__ float  g_rownll[BATCH];
__device__ int    g_label[BATCH];

// ---------------------------------------------------------------------------
// K0: label dtype autodetect (int64 vs int32) + materialize int32 labels.
// ---------------------------------------------------------------------------
__global__ void label_kernel(const int* __restrict__ raw) {
    __shared__ int s_or[16];
    int tid = threadIdx.x;
    int v = (tid & 1) ? raw[tid] : 0;
#pragma unroll
    for (int o = 16; o; o >>= 1) v |= __shfl_xor_sync(0xffffffffu, v, o);
    if ((tid & 31) == 0) s_or[tid >> 5] = v;
    __syncthreads();
    if (tid < 16) {
        int w = s_or[tid];
#pragma unroll
        for (int o = 8; o; o >>= 1) w |= __shfl_xor_sync(0xffffu, w, o);
        if (tid == 0) s_or[0] = w;
    }
    __syncthreads();
    bool is64 = (s_or[0] == 0);
    g_label[tid] = is64 ? raw[2 * tid] : raw[tid];
}

// ---------------------------------------------------------------------------
// K1a: W prep — normalize rows (fp32) + fp16 RNE convert. One warp per row.
// ---------------------------------------------------------------------------
__global__ void wprep_kernel(const float* __restrict__ w) {
    int gw   = (blockIdx.x * blockDim.x + threadIdx.x) >> 5;
    int lane = threadIdx.x & 31;
    if (gw >= NUM_CLASSES) return;
    const float4* row = (const float4*)(w + (size_t)gw * EMBED);
    float4 v[4];
    float s = 0.f;
#pragma unroll
    for (int i = 0; i < 4; i++) {
        v[i] = row[lane + i * 32];
        s += v[i].x * v[i].x + v[i].y * v[i].y + v[i].z * v[i].z + v[i].w * v[i].w;
    }
#pragma unroll
    for (int o = 16; o; o >>= 1) s += __shfl_xor_sync(0xffffffffu, s, o);
    float rn = 1.0f / fmaxf(__fsqrt_rn(s), 1e-12f);
    __half2* dst = (__half2*)(g_wh + (size_t)gw * EMBED);
#pragma unroll
    for (int i = 0; i < 4; i++) {
        int g2 = (lane + i * 32) * 2;
        dst[g2 + 0] = __floats2half2_rn(v[i].x * rn, v[i].y * rn);
        dst[g2 + 1] = __floats2half2_rn(v[i].z * rn, v[i].w * rn);
    }
}

// K1b: X prep — fp16 RNE convert.
__global__ void xprep_kernel(const float* __restrict__ x) {
    int i = blockIdx.x * 256 + threadIdx.x;   // over BATCH*EMBED/2
    float2 v = ((const float2*)x)[i];
    ((__half2*)g_xh)[i] = __floats2half2_rn(v.x, v.y);
}

// ---------------------------------------------------------------------------
// K2: fp16 GEMM (mma.sync m16n8k16, fp32 accum) + ArcFace epilogue.
//   cos[m,n] = Xh[m,:] . Wh[n,:]
// Tiles: BM=128, BN=128, BK=32 halves. 256 threads, 8 warps 2x4,
// warp tile 64x32. cp.async double-buffered; smem rows padded to 40 halves.
// ---------------------------------------------------------------------------
#define BM 128
#define BN 128
#define BK 32
#define ST 40              // halves per smem row (32 + 8 pad), 80B stride
#define NKT (EMBED / BK)   // 16

__device__ __forceinline__ void cp_async16(void* smem, const void* gsrc, bool pred) {
    uint32_t sa = (uint32_t)__cvta_generic_to_shared(smem);
    int sz = pred ? 16 : 0;
    asm volatile("cp.async.cg.shared.global [%0], [%1], 16, %2;\n"
                 :: "r"(sa), "l"(gsrc), "r"(sz));
}

__device__ __forceinline__ void mma_f16(float* d, const uint32_t* a, const uint32_t* b) {
    asm volatile(
        "mma.sync.aligned.m16n8k16.row.col.f32.f16.f16.f32 "
        "{%0,%1,%2,%3}, {%4,%5,%6,%7}, {%8,%9}, {%0,%1,%2,%3};\n"
        : "+f"(d[0]), "+f"(d[1]), "+f"(d[2]), "+f"(d[3])
        : "r"(a[0]), "r"(a[1]), "r"(a[2]), "r"(a[3]), "r"(b[0]), "r"(b[1]));
}

__device__ __forceinline__ float arcface_val(float c, bool is_label) {
    if (is_label) {
        float s2 = fminf(fmaxf(1.0f - c * c, 0.0f), 1.0f);
        float phi = c * COS_M - sqrtf(s2) * SIN_M;
        c = (c > TH_V) ? phi : (c - MM_V);
    }
    return c * S_SCALE;
}

__global__ void __launch_bounds__(256, 2)
arcface_gemm_f16(float* __restrict__ out) {
    const int m0 = blockIdx.x * BM;   // 4 batch tiles (fast dim -> W reuse in L2)
    const int n0 = blockIdx.y * BN;   // 782 class tiles
    const int tid  = threadIdx.x;
    const int warp = tid >> 5, lane = tid & 31;
    const int wm = warp >> 2, wn = warp & 3;    // 2 x 4 warp grid
    const int grp = lane >> 2, tig = lane & 3;

    __shared__ __half As[2][BM * ST];
    __shared__ __half Bs[2][BM * ST];

    float acc[4][4][4];
#pragma unroll
    for (int i = 0; i < 4; i++)
#pragma unroll
        for (int j = 0; j < 4; j++)
#pragma unroll
            for (int k = 0; k < 4; k++) acc[i][j][k] = 0.f;

    // loader: 128 rows x 64B = 4 x 16B chunks per row; 512 chunks over
    // 256 threads -> 2 each, for A and B.
    auto load_tiles = [&](int kt, int buf) {
#pragma unroll
        for (int i = 0; i < 2; i++) {
            int idx = tid + i * 256;
            int row = idx >> 2;
            int c8  = (idx & 3) * 8;   // half offset of the 16B chunk
            cp_async16(&As[buf][row * ST + c8],
                       g_xh + (size_t)(m0 + row) * EMBED + kt * BK + c8, true);
            bool p = (n0 + row) < NUM_CLASSES;
            cp_async16(&Bs[buf][row * ST + c8],
                       g_wh + (size_t)(n0 + row) * EMBED + kt * BK + c8, p);
        }
        asm volatile("cp.async.commit_group;\n");
    };

    load_tiles(0, 0);

    for (int kt = 0; kt < NKT; kt++) {
        if (kt + 1 < NKT) {
            load_tiles(kt + 1, (kt + 1) & 1);
            asm volatile("cp.async.wait_group 1;\n");
        } else {
            asm volatile("cp.async.wait_group 0;\n");
        }
        __syncthreads();

        const __half* Ab = As[kt & 1];
        const __half* Bb = Bs[kt & 1];
#pragma unroll
        for (int kk = 0; kk < BK / 16; kk++) {
            int k0 = kk * 16;
            uint32_t af[4][4], bf[4][2];
#pragma unroll
            for (int mt = 0; mt < 4; mt++) {
                int r = wm * 64 + mt * 16 + grp;
                af[mt][0] = *(const uint32_t*)&Ab[r * ST + k0 + 2 * tig];
                af[mt][1] = *(const uint32_t*)&Ab[(r + 8) * ST + k0 + 2 * tig];
                af[mt][2] = *(const uint32_t*)&Ab[r * ST + k0 + 2 * tig + 8];
                af[mt][3] = *(const uint32_t*)&Ab[(r + 8) * ST + k0 + 2 * tig + 8];
            }
#pragma unroll
            for (int nt = 0; nt < 4; nt++) {
                int c = wn * 32 + nt * 8 + grp;
                bf[nt][0] = *(const uint32_t*)&Bb[c * ST + k0 + 2 * tig];
                bf[nt][1] = *(const uint32_t*)&Bb[c * ST + k0 + 2 * tig + 8];
            }
#pragma unroll
            for (int mt = 0; mt < 4; mt++)
#pragma unroll
                for (int nt = 0; nt < 4; nt++)
                    mma_f16(acc[mt][nt], af[mt], bf[nt]);
        }
        __syncthreads();
    }

    // Epilogue: ArcFace margin at label column, * S.
#pragma unroll
    for (int mt = 0; mt < 4; mt++) {
        int m_lo = m0 + wm * 64 + mt * 16 + grp;
        int m_hi = m_lo + 8;
        int lbl_lo = g_label[m_lo];
        int lbl_hi = g_label[m_hi];
#pragma unroll
        for (int nt = 0; nt < 4; nt++) {
            int n = n0 + wn * 32 + nt * 8 + 2 * tig;
            float* a = acc[mt][nt];
            if (n < NUM_CLASSES) {
                out[(size_t)m_lo * NUM_CLASSES + n] = arcface_val(a[0], n == lbl_lo);
                out[(size_t)m_hi * NUM_CLASSES + n] = arcface_val(a[2], n == lbl_hi);
            }
            if (n + 1 < NUM_CLASSES) {
                out[(size_t)m_lo * NUM_CLASSES + n + 1] = arcface_val(a[1], (n + 1) == lbl_lo);
                out[(size_t)m_hi * NUM_CLASSES + n + 1] = arcface_val(a[3], (n + 1) == lbl_hi);
            }
        }
    }
}

// ---------------------------------------------------------------------------
// K3: per-row online logsumexp over 100000 logits -> per-row NLL.
// ---------------------------------------------------------------------------
__global__ void lse_kernel(const float* __restrict__ logits) {
    const int row = blockIdx.x;
    const int tid = threadIdx.x;
    const float4* p = (const float4*)(logits + (size_t)row * NUM_CLASSES);
    const int n4 = NUM_CLASSES / 4;

    float m = -INFINITY, s = 0.f;
    for (int i = tid; i < n4; i += 512) {
        float4 v = p[i];
        float mx = fmaxf(fmaxf(v.x, v.y), fmaxf(v.z, v.w));
        if (mx > m) { s *= __expf(m - mx); m = mx; }
        s += __expf(v.x - m) + __expf(v.y - m) + __expf(v.z - m) + __expf(v.w - m);
    }

    __shared__ float sm[512];
    __shared__ float ss[512];
    sm[tid] = m; ss[tid] = s;
    __syncthreads();
    for (int o = 256; o; o >>= 1) {
        if (tid < o) {
            float m1 = sm[tid], s1 = ss[tid];
            float m2 = sm[tid + o], s2 = ss[tid + o];
            float mm = fmaxf(m1, m2);
            sm[tid] = mm;
            ss[tid] = s1 * __expf(m1 - mm) + s2 * __expf(m2 - mm);
        }
        __syncthreads();
    }
    if (tid == 0) {
        float logZ = sm[0] + __logf(ss[0]);
        int lbl = g_label[row];
        g_rownll[row] = logZ - logits[(size_t)row * NUM_CLASSES + lbl];
    }
}

// ---------------------------------------------------------------------------
// K4: loss = mean(rownll).
// ---------------------------------------------------------------------------
__global__ void loss_kernel(float* __restrict__ out, int out_size) {
    __shared__ float sm[BATCH];
    sm[threadIdx.x] = g_rownll[threadIdx.x];
    __syncthreads();
    for (int o = 256; o; o >>= 1) {
        if (threadIdx.x < o) sm[threadIdx.x] += sm[threadIdx.x + o];
        __syncthreads();
    }
    if (threadIdx.x == 0) {
        long long total = (long long)BATCH * NUM_CLASSES;
        if ((long long)out_size > total)
            out[total] = sm[0] * (1.0f / BATCH);
    }
}

// ---------------------------------------------------------------------------
extern "C" void kernel_launch(void* const* d_in, const int* in_sizes, int n_in,
                              void* d_out, int out_size) {
    const float* X        = (const float*)d_in[0];
    const int*   labelRaw = (const int*)d_in[1];
    const float* W        = (const float*)d_in[2];
    float* out = (float*)d_out;

    label_kernel<<<1, BATCH>>>(labelRaw);
    xprep_kernel<<<BATCH * EMBED / 512, 256>>>(X);
    wprep_kernel<<<NUM_CLASSES / 8, 256>>>(W);

    dim3 grid(BATCH / BM, (NUM_CLASSES + BN - 1) / BN);  // (4, 782)
    arcface_gemm_f16<<<grid, 256>>>(out);

    lse_kernel<<<BATCH, 512>>>(out);
    loss_kernel<<<1, BATCH>>>(out, out_size);
}

// round 9
// speedup vs baseline: 3.8478x; 1.0323x over previous
#include <cuda_runtime.h>
#include <cuda_fp16.h>
#include <cstdint>

#define NUM_CLASSES 100000
#define BATCH 512
#define EMBED 512

#define S_SCALE 64.0f
#define COS_M 0.8775825618903728f
#define SIN_M 0.479425538604203f
#define TH_V (-0.8775825618903728f)
#define MM_V 0.23971276930210156f

// scratch (no allocations allowed)
__device__ __half g_wh[(size_t)NUM_CLASSES * EMBED];  // fp16(w / ||w||)
__device__ __half g_xh[BATCH * EMBED];                // fp16(x)
__device__ float  g_rownll[BATCH];
__device__ int    g_label[BATCH];

// ---------------------------------------------------------------------------
// K0: label dtype autodetect (int64 vs int32) + materialize int32 labels.
// ---------------------------------------------------------------------------
__global__ void label_kernel(const int* __restrict__ raw) {
    __shared__ int s_or[16];
    int tid = threadIdx.x;
    int v = (tid & 1) ? raw[tid] : 0;
#pragma unroll
    for (int o = 16; o; o >>= 1) v |= __shfl_xor_sync(0xffffffffu, v, o);
    if ((tid & 31) == 0) s_or[tid >> 5] = v;
    __syncthreads();
    if (tid < 16) {
        int w = s_or[tid];
#pragma unroll
        for (int o = 8; o; o >>= 1) w |= __shfl_xor_sync(0xffffu, w, o);
        if (tid == 0) s_or[0] = w;
    }
    __syncthreads();
    bool is64 = (s_or[0] == 0);
    g_label[tid] = is64 ? raw[2 * tid] : raw[tid];
}

// ---------------------------------------------------------------------------
// K1a: W prep — normalize rows (fp32) + fp16 RNE convert. One warp per row.
// ---------------------------------------------------------------------------
__global__ void wprep_kernel(const float* __restrict__ w) {
    int gw   = (blockIdx.x * blockDim.x + threadIdx.x) >> 5;
    int lane = threadIdx.x & 31;
    if (gw >= NUM_CLASSES) return;
    const float4* row = (const float4*)(w + (size_t)gw * EMBED);
    float4 v[4];
    float s = 0.f;
#pragma unroll
    for (int i = 0; i < 4; i++) {
        v[i] = row[lane + i * 32];
        s += v[i].x * v[i].x + v[i].y * v[i].y + v[i].z * v[i].z + v[i].w * v[i].w;
    }
#pragma unroll
    for (int o = 16; o; o >>= 1) s += __shfl_xor_sync(0xffffffffu, s, o);
    float rn = 1.0f / fmaxf(__fsqrt_rn(s), 1e-12f);
    __half2* dst = (__half2*)(g_wh + (size_t)gw * EMBED);
#pragma unroll
    for (int i = 0; i < 4; i++) {
        int g2 = (lane + i * 32) * 2;
        dst[g2 + 0] = __floats2half2_rn(v[i].x * rn, v[i].y * rn);
        dst[g2 + 1] = __floats2half2_rn(v[i].z * rn, v[i].w * rn);
    }
}

// K1b: X prep — fp16 RNE convert.
__global__ void xprep_kernel(const float* __restrict__ x) {
    int i = blockIdx.x * 256 + threadIdx.x;   // over BATCH*EMBED/2
    float2 v = ((const float2*)x)[i];
    ((__half2*)g_xh)[i] = __floats2half2_rn(v.x, v.y);
}

// ---------------------------------------------------------------------------
// K2: fp16 GEMM (mma.sync m16n8k16, fp32 accum, ldmatrix fragments)
//     + ArcFace epilogue.
// Tiles: BM=128, BN=128, BK=32 halves. 256 threads, 8 warps 2x4,
// warp tile 64x32. cp.async double-buffered; smem rows padded to 40 halves
// (80B stride -> ldmatrix conflict-free: banks 0,20,8,28,16,4,24,12).
// ---------------------------------------------------------------------------
#define BM 128
#define BN 128
#define BK 32
#define ST 40              // halves per smem row (32 + 8 pad), 80B stride
#define NKT (EMBED / BK)   // 16

__device__ __forceinline__ uint32_t smem_u32(const void* p) {
    return (uint32_t)__cvta_generic_to_shared(p);
}
__device__ __forceinline__ void cp_async16(void* smem, const void* gsrc, bool pred) {
    uint32_t sa = smem_u32(smem);
    int sz = pred ? 16 : 0;
    asm volatile("cp.async.cg.shared.global [%0], [%1], 16, %2;\n"
                 :: "r"(sa), "l"(gsrc), "r"(sz));
}
__device__ __forceinline__ void ldsm_x4(uint32_t& r0, uint32_t& r1,
                                        uint32_t& r2, uint32_t& r3, uint32_t addr) {
    asm volatile("ldmatrix.sync.aligned.m8n8.x4.shared.b16 {%0,%1,%2,%3}, [%4];"
                 : "=r"(r0), "=r"(r1), "=r"(r2), "=r"(r3) : "r"(addr));
}
__device__ __forceinline__ void mma_f16(float* d, const uint32_t* a, const uint32_t* b) {
    asm volatile(
        "mma.sync.aligned.m16n8k16.row.col.f32.f16.f16.f32 "
        "{%0,%1,%2,%3}, {%4,%5,%6,%7}, {%8,%9}, {%0,%1,%2,%3};\n"
        : "+f"(d[0]), "+f"(d[1]), "+f"(d[2]), "+f"(d[3])
        : "r"(a[0]), "r"(a[1]), "r"(a[2]), "r"(a[3]), "r"(b[0]), "r"(b[1]));
}
__device__ __forceinline__ float arcface_val(float c, bool is_label) {
    if (is_label) {
        float s2 = fminf(fmaxf(1.0f - c * c, 0.0f), 1.0f);
        float phi = c * COS_M - sqrtf(s2) * SIN_M;
        c = (c > TH_V) ? phi : (c - MM_V);
    }
    return c * S_SCALE;
}

__global__ void __launch_bounds__(256, 2)
arcface_gemm_f16(float* __restrict__ out) {
    const int m0 = blockIdx.x * BM;   // 4 batch tiles (fast dim -> W reuse in L2)
    const int n0 = blockIdx.y * BN;   // 782 class tiles
    const int tid  = threadIdx.x;
    const int warp = tid >> 5, lane = tid & 31;
    const int wm = warp >> 2, wn = warp & 3;    // 2 x 4 warp grid
    const int grp = lane >> 2, tig = lane & 3;

    __shared__ __half As[2][BM * ST];
    __shared__ __half Bs[2][BM * ST];

    float acc[4][4][4];
#pragma unroll
    for (int i = 0; i < 4; i++)
#pragma unroll
        for (int j = 0; j < 4; j++)
#pragma unroll
            for (int k = 0; k < 4; k++) acc[i][j][k] = 0.f;

    // ldmatrix per-lane address offsets (bytes within a tile buffer)
    const int g8 = lane >> 3, rw = lane & 7;
    // A x4: g0:(m+0..7,k0) g1:(m+8..15,k0) g2:(m+0..7,k8) g3:(m+8..15,k8)
    const uint32_t a_off = (uint32_t)(((wm * 64 + (g8 & 1) * 8 + rw) * ST
                                       + (g8 >> 1) * 8) * 2);
    // B x4 (nt pair p): g0:(nt=2p,k0) g1:(2p,k8) g2:(2p+1,k0) g3:(2p+1,k8)
    const uint32_t b_off0 = (uint32_t)(((wn * 32 + (g8 >> 1) * 8 + rw) * ST
                                        + (g8 & 1) * 8) * 2);
    const uint32_t b_off1 = b_off0 + 16 * ST * 2;

    // loader: 128 rows x 64B = 4 x 16B chunks per row; 512 chunks over
    // 256 threads -> 2 each, for A and B.
    auto load_tiles = [&](int kt, int buf) {
#pragma unroll
        for (int i = 0; i < 2; i++) {
            int idx = tid + i * 256;
            int row = idx >> 2;
            int c8  = (idx & 3) * 8;   // half offset of the 16B chunk
            cp_async16(&As[buf][row * ST + c8],
                       g_xh + (size_t)(m0 + row) * EMBED + kt * BK + c8, true);
            bool p = (n0 + row) < NUM_CLASSES;
            cp_async16(&Bs[buf][row * ST + c8],
                       g_wh + (size_t)(n0 + row) * EMBED + kt * BK + c8, p);
        }
        asm volatile("cp.async.commit_group;\n");
    };

    load_tiles(0, 0);

    for (int kt = 0; kt < NKT; kt++) {
        if (kt + 1 < NKT) {
            load_tiles(kt + 1, (kt + 1) & 1);
            asm volatile("cp.async.wait_group 1;\n");
        } else {
            asm volatile("cp.async.wait_group 0;\n");
        }
        __syncthreads();

        const uint32_t Ab = smem_u32(&As[kt & 1][0]);
        const uint32_t Bb = smem_u32(&Bs[kt & 1][0]);
#pragma unroll
        for (int kk = 0; kk < BK / 16; kk++) {
            const uint32_t kb = kk * 32;   // 16 halves = 32 bytes
            uint32_t af[4][4], bf[4][2];
            ldsm_x4(bf[0][0], bf[0][1], bf[1][0], bf[1][1], Bb + b_off0 + kb);
            ldsm_x4(bf[2][0], bf[2][1], bf[3][0], bf[3][1], Bb + b_off1 + kb);
#pragma unroll
            for (int mt = 0; mt < 4; mt++)
                ldsm_x4(af[mt][0], af[mt][1], af[mt][2], af[mt][3],
                        Ab + a_off + mt * (16 * ST * 2) + kb);
#pragma unroll
            for (int mt = 0; mt < 4; mt++)
#pragma unroll
                for (int nt = 0; nt < 4; nt++)
                    mma_f16(acc[mt][nt], af[mt], bf[nt]);
        }
        __syncthreads();
    }

    // Epilogue: ArcFace margin at label column, * S.
#pragma unroll
    for (int mt = 0; mt < 4; mt++) {
        int m_lo = m0 + wm * 64 + mt * 16 + grp;
        int m_hi = m_lo + 8;
        int lbl_lo = g_label[m_lo];
        int lbl_hi = g_label[m_hi];
#pragma unroll
        for (int nt = 0; nt < 4; nt++) {
            int n = n0 + wn * 32 + nt * 8 + 2 * tig;
            float* a = acc[mt][nt];
            if (n < NUM_CLASSES) {
                out[(size_t)m_lo * NUM_CLASSES + n] = arcface_val(a[0], n == lbl_lo);
                out[(size_t)m_hi * NUM_CLASSES + n] = arcface_val(a[2], n == lbl_hi);
            }
            if (n + 1 < NUM_CLASSES) {
                out[(size_t)m_lo * NUM_CLASSES + n + 1] = arcface_val(a[1], (n + 1) == lbl_lo);
                out[(size_t)m_hi * NUM_CLASSES + n + 1] = arcface_val(a[3], (n + 1) == lbl_hi);
            }
        }
    }
}

// ---------------------------------------------------------------------------
// K3: per-row online logsumexp over 100000 logits -> per-row NLL.
// ---------------------------------------------------------------------------
__global__ void lse_kernel(const float* __restrict__ logits) {
    const int row = blockIdx.x;
    const int tid = threadIdx.x;
    const float4* p = (const float4*)(logits + (size_t)row * NUM_CLASSES);
    const int n4 = NUM_CLASSES / 4;

    float m = -INFINITY, s = 0.f;
    for (int i = tid; i < n4; i += 512) {
        float4 v = p[i];
        float mx = fmaxf(fmaxf(v.x, v.y), fmaxf(v.z, v.w));
        if (mx > m) { s *= __expf(m - mx); m = mx; }
        s += __expf(v.x - m) + __expf(v.y - m) + __expf(v.z - m) + __expf(v.w - m);
    }

    __shared__ float sm[512];
    __shared__ float ss[512];
    sm[tid] = m; ss[tid] = s;
    __syncthreads();
    for (int o = 256; o; o >>= 1) {
        if (tid < o) {
            float m1 = sm[tid], s1 = ss[tid];
            float m2 = sm[tid + o], s2 = ss[tid + o];
            float mm = fmaxf(m1, m2);
            sm[tid] = mm;
            ss[tid] = s1 * __expf(m1 - mm) + s2 * __expf(m2 - mm);
        }
        __syncthreads();
    }
    if (tid == 0) {
        float logZ = sm[0] + __logf(ss[0]);
        int lbl = g_label[row];
        g_rownll[row] = logZ - logits[(size_t)row * NUM_CLASSES + lbl];
    }
}

// ---------------------------------------------------------------------------
// K4: loss = mean(rownll).
// ---------------------------------------------------------------------------
__global__ void loss_kernel(float* __restrict__ out, int out_size) {
    __shared__ float sm[BATCH];
    sm[threadIdx.x] = g_rownll[threadIdx.x];
    __syncthreads();
    for (int o = 256; o; o >>= 1) {
        if (threadIdx.x < o) sm[threadIdx.x] += sm[threadIdx.x + o];
        __syncthreads();
    }
    if (threadIdx.x == 0) {
        long long total = (long long)BATCH * NUM_CLASSES;
        if ((long long)out_size > total)
            out[total] = sm[0] * (1.0f / BATCH);
    }
}

// ---------------------------------------------------------------------------
extern "C" void kernel_launch(void* const* d_in, const int* in_sizes, int n_in,
                              void* d_out, int out_size) {
    const float* X        = (const float*)d_in[0];
    const int*   labelRaw = (const int*)d_in[1];
    const float* W        = (const float*)d_in[2];
    float* out = (float*)d_out;

    label_kernel<<<1, BATCH>>>(labelRaw);
    xprep_kernel<<<BATCH * EMBED / 512, 256>>>(X);
    wprep_kernel<<<NUM_CLASSES / 8, 256>>>(W);

    dim3 grid(BATCH / BM, (NUM_CLASSES + BN - 1) / BN);  // (4, 782)
    arcface_gemm_f16<<<grid, 256>>>(out);

    lse_kernel<<<BATCH, 512>>>(out);
    loss_kernel<<<1, BATCH>>>(out, out_size);
}

// round 10
// speedup vs baseline: 3.8925x; 1.0116x over previous
#include <cuda_runtime.h>
#include <cuda_fp16.h>
#include <cstdint>

#define NUM_CLASSES 100000
#define BATCH 512
#define EMBED 512

#define S_SCALE 64.0f
#define COS_M 0.8775825618903728f
#define SIN_M 0.479425538604203f
#define TH_V (-0.8775825618903728f)
#define MM_V 0.23971276930210156f

// scratch (no allocations allowed)
__device__ __half g_wh[(size_t)NUM_CLASSES * EMBED];  // fp16(w / ||w||)
__device__ __half g_xh[BATCH * EMBED];                // fp16(x)
__device__ float  g_rownll[BATCH];
__device__ int    g_label[BATCH];

// ---------------------------------------------------------------------------
// K0: label dtype autodetect (int64 vs int32) + materialize int32 labels.
// ---------------------------------------------------------------------------
__global__ void label_kernel(const int* __restrict__ raw) {
    __shared__ int s_or[16];
    int tid = threadIdx.x;
    int v = (tid & 1) ? raw[tid] : 0;
#pragma unroll
    for (int o = 16; o; o >>= 1) v |= __shfl_xor_sync(0xffffffffu, v, o);
    if ((tid & 31) == 0) s_or[tid >> 5] = v;
    __syncthreads();
    if (tid < 16) {
        int w = s_or[tid];
#pragma unroll
        for (int o = 8; o; o >>= 1) w |= __shfl_xor_sync(0xffffu, w, o);
        if (tid == 0) s_or[0] = w;
    }
    __syncthreads();
    bool is64 = (s_or[0] == 0);
    g_label[tid] = is64 ? raw[2 * tid] : raw[tid];
}

// ---------------------------------------------------------------------------
// K1a: W prep — normalize rows (fp32) + fp16 RNE convert. One warp per row.
// ---------------------------------------------------------------------------
__global__ void wprep_kernel(const float* __restrict__ w) {
    int gw   = (blockIdx.x * blockDim.x + threadIdx.x) >> 5;
    int lane = threadIdx.x & 31;
    if (gw >= NUM_CLASSES) return;
    const float4* row = (const float4*)(w + (size_t)gw * EMBED);
    float4 v[4];
    float s = 0.f;
#pragma unroll
    for (int i = 0; i < 4; i++) {
        v[i] = row[lane + i * 32];
        s += v[i].x * v[i].x + v[i].y * v[i].y + v[i].z * v[i].z + v[i].w * v[i].w;
    }
#pragma unroll
    for (int o = 16; o; o >>= 1) s += __shfl_xor_sync(0xffffffffu, s, o);
    float rn = 1.0f / fmaxf(__fsqrt_rn(s), 1e-12f);
    __half2* dst = (__half2*)(g_wh + (size_t)gw * EMBED);
#pragma unroll
    for (int i = 0; i < 4; i++) {
        int g2 = (lane + i * 32) * 2;
        dst[g2 + 0] = __floats2half2_rn(v[i].x * rn, v[i].y * rn);
        dst[g2 + 1] = __floats2half2_rn(v[i].z * rn, v[i].w * rn);
    }
}

// K1b: X prep — fp16 RNE convert.
__global__ void xprep_kernel(const float* __restrict__ x) {
    int i = blockIdx.x * 256 + threadIdx.x;   // over BATCH*EMBED/2
    float2 v = ((const float2*)x)[i];
    ((__half2*)g_xh)[i] = __floats2half2_rn(v.x, v.y);
}

// ---------------------------------------------------------------------------
// K2: fp16 GEMM (mma.sync m16n8k16, fp32 accum, ldmatrix fragments)
//     + ArcFace epilogue.
// Tiles: BM=128, BN=128, BK=32 halves. 256 threads, 8 warps 2x4,
// warp tile 64x32. 3-stage cp.async pipeline, ONE __syncthreads per k-tile.
// smem rows padded to 40 halves (80B stride -> ldmatrix conflict-free).
// ---------------------------------------------------------------------------
#define BM 128
#define BN 128
#define BK 32
#define ST 40              // halves per smem row (32 + 8 pad), 80B stride
#define NKT (EMBED / BK)   // 16
#define TILE_H (BM * ST)   // halves per tile buffer (5120)
#define DSMEM_BYTES (3 * 2 * TILE_H * 2)   // 3 stages x (A+B) x 2B = 61440

extern __shared__ __half dsm[];

__device__ __forceinline__ uint32_t smem_u32(const void* p) {
    return (uint32_t)__cvta_generic_to_shared(p);
}
__device__ __forceinline__ void cp_async16(void* smem, const void* gsrc, bool pred) {
    uint32_t sa = smem_u32(smem);
    int sz = pred ? 16 : 0;
    asm volatile("cp.async.cg.shared.global [%0], [%1], 16, %2;\n"
                 :: "r"(sa), "l"(gsrc), "r"(sz));
}
__device__ __forceinline__ void ldsm_x4(uint32_t& r0, uint32_t& r1,
                                        uint32_t& r2, uint32_t& r3, uint32_t addr) {
    asm volatile("ldmatrix.sync.aligned.m8n8.x4.shared.b16 {%0,%1,%2,%3}, [%4];"
                 : "=r"(r0), "=r"(r1), "=r"(r2), "=r"(r3) : "r"(addr));
}
__device__ __forceinline__ void mma_f16(float* d, const uint32_t* a, const uint32_t* b) {
    asm volatile(
        "mma.sync.aligned.m16n8k16.row.col.f32.f16.f16.f32 "
        "{%0,%1,%2,%3}, {%4,%5,%6,%7}, {%8,%9}, {%0,%1,%2,%3};\n"
        : "+f"(d[0]), "+f"(d[1]), "+f"(d[2]), "+f"(d[3])
        : "r"(a[0]), "r"(a[1]), "r"(a[2]), "r"(a[3]), "r"(b[0]), "r"(b[1]));
}
__device__ __forceinline__ float arcface_val(float c, bool is_label) {
    if (is_label) {
        float s2 = fminf(fmaxf(1.0f - c * c, 0.0f), 1.0f);
        float phi = c * COS_M - sqrtf(s2) * SIN_M;
        c = (c > TH_V) ? phi : (c - MM_V);
    }
    return c * S_SCALE;
}

__global__ void __launch_bounds__(256, 2)
arcface_gemm_f16(float* __restrict__ out) {
    const int m0 = blockIdx.x * BM;   // 4 batch tiles (fast dim -> W reuse in L2)
    const int n0 = blockIdx.y * BN;   // 782 class tiles
    const int tid  = threadIdx.x;
    const int warp = tid >> 5, lane = tid & 31;
    const int wm = warp >> 2, wn = warp & 3;    // 2 x 4 warp grid
    const int grp = lane >> 2, tig = lane & 3;

    __half* As = dsm;                 // 3 x TILE_H
    __half* Bs = dsm + 3 * TILE_H;    // 3 x TILE_H

    float acc[4][4][4];
#pragma unroll
    for (int i = 0; i < 4; i++)
#pragma unroll
        for (int j = 0; j < 4; j++)
#pragma unroll
            for (int k = 0; k < 4; k++) acc[i][j][k] = 0.f;

    // ldmatrix per-lane address offsets (bytes within a tile buffer)
    const int g8 = lane >> 3, rw = lane & 7;
    const uint32_t a_off = (uint32_t)(((wm * 64 + (g8 & 1) * 8 + rw) * ST
                                       + (g8 >> 1) * 8) * 2);
    const uint32_t b_off0 = (uint32_t)(((wn * 32 + (g8 >> 1) * 8 + rw) * ST
                                        + (g8 & 1) * 8) * 2);
    const uint32_t b_off1 = b_off0 + 16 * ST * 2;

    // loader: 128 rows x 64B = 4 x 16B chunks per row; 512 chunks over
    // 256 threads -> 2 each, for A and B.
    auto load_tiles = [&](int kt) {
        const int buf = kt % 3;
#pragma unroll
        for (int i = 0; i < 2; i++) {
            int idx = tid + i * 256;
            int row = idx >> 2;
            int c8  = (idx & 3) * 8;   // half offset of the 16B chunk
            cp_async16(&As[buf * TILE_H + row * ST + c8],
                       g_xh + (size_t)(m0 + row) * EMBED + kt * BK + c8, true);
            bool p = (n0 + row) < NUM_CLASSES;
            cp_async16(&Bs[buf * TILE_H + row * ST + c8],
                       g_wh + (size_t)(n0 + row) * EMBED + kt * BK + c8, p);
        }
        asm volatile("cp.async.commit_group;\n");
    };

    load_tiles(0);
    load_tiles(1);

    for (int kt = 0; kt < NKT; kt++) {
        if (kt < NKT - 2) asm volatile("cp.async.wait_group 1;\n");
        else              asm volatile("cp.async.wait_group 0;\n");
        __syncthreads();   // data kt visible everywhere; compute kt-1 done by all

        if (kt + 2 < NKT) load_tiles(kt + 2);   // buf (kt+2)%3 == (kt-1)%3: free

        const uint32_t Ab = smem_u32(&As[(kt % 3) * TILE_H]);
        const uint32_t Bb = smem_u32(&Bs[(kt % 3) * TILE_H]);
#pragma unroll
        for (int kk = 0; kk < BK / 16; kk++) {
            const uint32_t kb = kk * 32;   // 16 halves = 32 bytes
            uint32_t af[4][4], bf[4][2];
            ldsm_x4(bf[0][0], bf[0][1], bf[1][0], bf[1][1], Bb + b_off0 + kb);
            ldsm_x4(bf[2][0], bf[2][1], bf[3][0], bf[3][1], Bb + b_off1 + kb);
#pragma unroll
            for (int mt = 0; mt < 4; mt++)
                ldsm_x4(af[mt][0], af[mt][1], af[mt][2], af[mt][3],
                        Ab + a_off + mt * (16 * ST * 2) + kb);
#pragma unroll
            for (int mt = 0; mt < 4; mt++)
#pragma unroll
                for (int nt = 0; nt < 4; nt++)
                    mma_f16(acc[mt][nt], af[mt], bf[nt]);
        }
    }

    // Epilogue: ArcFace margin at label column, * S.
#pragma unroll
    for (int mt = 0; mt < 4; mt++) {
        int m_lo = m0 + wm * 64 + mt * 16 + grp;
        int m_hi = m_lo + 8;
        int lbl_lo = g_label[m_lo];
        int lbl_hi = g_label[m_hi];
#pragma unroll
        for (int nt = 0; nt < 4; nt++) {
            int n = n0 + wn * 32 + nt * 8 + 2 * tig;
            float* a = acc[mt][nt];
            if (n < NUM_CLASSES) {
                out[(size_t)m_lo * NUM_CLASSES + n] = arcface_val(a[0], n == lbl_lo);
                out[(size_t)m_hi * NUM_CLASSES + n] = arcface_val(a[2], n == lbl_hi);
            }
            if (n + 1 < NUM_CLASSES) {
                out[(size_t)m_lo * NUM_CLASSES + n + 1] = arcface_val(a[1], (n + 1) == lbl_lo);
                out[(size_t)m_hi * NUM_CLASSES + n + 1] = arcface_val(a[3], (n + 1) == lbl_hi);
            }
        }
    }
}

// ---------------------------------------------------------------------------
// K3: per-row online logsumexp over 100000 logits -> per-row NLL.
// ---------------------------------------------------------------------------
__global__ void lse_kernel(const float* __restrict__ logits) {
    const int row = blockIdx.x;
    const int tid = threadIdx.x;
    const float4* p = (const float4*)(logits + (size_t)row * NUM_CLASSES);
    const int n4 = NUM_CLASSES / 4;

    float m = -INFINITY, s = 0.f;
    for (int i = tid; i < n4; i += 512) {
        float4 v = p[i];
        float mx = fmaxf(fmaxf(v.x, v.y), fmaxf(v.z, v.w));
        if (mx > m) { s *= __expf(m - mx); m = mx; }
        s += __expf(v.x - m) + __expf(v.y - m) + __expf(v.z - m) + __expf(v.w - m);
    }

    __shared__ float sm[512];
    __shared__ float ss[512];
    sm[tid] = m; ss[tid] = s;
    __syncthreads();
    for (int o = 256; o; o >>= 1) {
        if (tid < o) {
            float m1 = sm[tid], s1 = ss[tid];
            float m2 = sm[tid + o], s2 = ss[tid + o];
            float mm = fmaxf(m1, m2);
            sm[tid] = mm;
            ss[tid] = s1 * __expf(m1 - mm) + s2 * __expf(m2 - mm);
        }
        __syncthreads();
    }
    if (tid == 0) {
        float logZ = sm[0] + __logf(ss[0]);
        int lbl = g_label[row];
        g_rownll[row] = logZ - logits[(size_t)row * NUM_CLASSES + lbl];
    }
}

// ---------------------------------------------------------------------------
// K4: loss = mean(rownll).
// ---------------------------------------------------------------------------
__global__ void loss_kernel(float* __restrict__ out, int out_size) {
    __shared__ float sm[BATCH];
    sm[threadIdx.x] = g_rownll[threadIdx.x];
    __syncthreads();
    for (int o = 256; o; o >>= 1) {
        if (threadIdx.x < o) sm[threadIdx.x] += sm[threadIdx.x + o];
        __syncthreads();
    }
    if (threadIdx.x == 0) {
        long long total = (long long)BATCH * NUM_CLASSES;
        if ((long long)out_size > total)
            out[total] = sm[0] * (1.0f / BATCH);
    }
}

// ---------------------------------------------------------------------------
extern "C" void kernel_launch(void* const* d_in, const int* in_sizes, int n_in,
                              void* d_out, int out_size) {
    const float* X        = (const float*)d_in[0];
    const int*   labelRaw = (const int*)d_in[1];
    const float* W        = (const float*)d_in[2];
    float* out = (float*)d_out;

    static bool attr_done = false;
    if (!attr_done) {
        cudaFuncSetAttribute(arcface_gemm_f16,
                             cudaFuncAttributeMaxDynamicSharedMemorySize, DSMEM_BYTES);
        attr_done = true;
    }

    label_kernel<<<1, BATCH>>>(labelRaw);
    xprep_kernel<<<BATCH * EMBED / 512, 256>>>(X);
    wprep_kernel<<<NUM_CLASSES / 8, 256>>>(W);

    dim3 grid(BATCH / BM, (NUM_CLASSES + BN - 1) / BN);  // (4, 782)
    arcface_gemm_f16<<<grid, 256, DSMEM_BYTES>>>(out);

    lse_kernel<<<BATCH, 512>>>(out);
    loss_kernel<<<1, BATCH>>>(out, out_size);
}